// round 7
// baseline (speedup 1.0000x reference)
#include <cuda_runtime.h>
#include <cuda_bf16.h>

// Collapsed forward (linear in context_batch -> batch reduces to 2 scalars):
//   u_i = r_i @ Wv   (r0,r1 = rows of ctx_w, r2 = ctx_b; u2 += bv)
//   w_i = u_i @ Wo   (w2 += bo)
//   P_i[s,h] = w_i @ Whead[s,h]  (+bias into P2)
//   out[h,b,:] = c0[b]*P0 + c1[b]*P1 + P2   (selected by sid[b])
//
// R7: one 8-CTA CLUSTER, HW barrier.cluster instead of software atomic grid
// barriers (which serialized ~1.8us each at 128 CTAs). Only 2 cluster syncs:
// stage C (heads) and the batch combine are fused into one CTA each.

#define D_MODEL 512
#define NB 16
#define NOUT 64
#define NCTA 8

__device__ float g_u[3 * D_MODEL];
__device__ float g_w[3 * D_MODEL];

#define CLUSTER_SYNC_FENCED() do {                                   \
    __threadfence();                                                 \
    asm volatile("barrier.cluster.arrive.aligned;" ::: "memory");    \
    asm volatile("barrier.cluster.wait.aligned;"   ::: "memory");    \
} while (0)

__global__ void __cluster_dims__(NCTA, 1, 1) __launch_bounds__(256, 1)
hivemind_cluster(
    const float* __restrict__ cb,      // (16,2)
    const int*   __restrict__ sid,     // (16,)
    const float* __restrict__ ctx_w,   // (2,512)
    const float* __restrict__ ctx_b,   // (512,)
    const float* __restrict__ Wv,      // (512,512)
    const float* __restrict__ bv,      // (512,)
    const float* __restrict__ Wo,      // (512,512)
    const float* __restrict__ bo,      // (512,)
    const float* __restrict__ pred_w,  // (4,512,64)
    const float* __restrict__ pred_b,  // (4,64)
    const float* __restrict__ act_w,   // (4,512,64)
    const float* __restrict__ act_b,   // (4,64)
    float* __restrict__ out)           // [pred(16x64), act(16x64)]
{
    __shared__ float s_vec[3][D_MODEL];        // stage input vectors
    __shared__ float s_part[16][3][64];        // k-split partials
    __shared__ float s_P[3][NOUT];
    __shared__ float s_cb[NB * 2];
    __shared__ int   s_sid[NB];

    const int r  = blockIdx.x;       // cluster rank 0..7
    const int t  = threadIdx.x;      // 256 threads
    const int q  = t & 15;           // quad lane: 4 consecutive d/o columns
    const int ks = t >> 4;           // k-split 0..15 (32 k each)

    // preload tiny batch data once (used only in final stage)
    if (t < NB * 2) s_cb[t]  = cb[t];
    if (t < NB)     s_sid[t] = sid[t];

    // ================= Stage A: u_i = r_i @ Wv ==========================
    for (int k = t; k < D_MODEL; k += 256) {
        s_vec[0][k] = ctx_w[k];
        s_vec[1][k] = ctx_w[D_MODEL + k];
        s_vec[2][k] = ctx_b[k];
    }
    __syncthreads();
    {
        const int d0 = r * 64 + q * 4;
        float4 a0 = {0,0,0,0}, a1 = {0,0,0,0}, a2 = {0,0,0,0};
        #pragma unroll 8
        for (int i = 0; i < 32; ++i) {
            const int k = ks * 32 + i;
            const float4 w = *(const float4*)&Wv[k * D_MODEL + d0];
            const float x0 = s_vec[0][k], x1 = s_vec[1][k], x2 = s_vec[2][k];
            a0.x = fmaf(x0, w.x, a0.x); a0.y = fmaf(x0, w.y, a0.y);
            a0.z = fmaf(x0, w.z, a0.z); a0.w = fmaf(x0, w.w, a0.w);
            a1.x = fmaf(x1, w.x, a1.x); a1.y = fmaf(x1, w.y, a1.y);
            a1.z = fmaf(x1, w.z, a1.z); a1.w = fmaf(x1, w.w, a1.w);
            a2.x = fmaf(x2, w.x, a2.x); a2.y = fmaf(x2, w.y, a2.y);
            a2.z = fmaf(x2, w.z, a2.z); a2.w = fmaf(x2, w.w, a2.w);
        }
        *(float4*)&s_part[ks][0][q * 4] = a0;
        *(float4*)&s_part[ks][1][q * 4] = a1;
        *(float4*)&s_part[ks][2][q * 4] = a2;
    }
    __syncthreads();
    if (t < 192) {
        const int i = t >> 6, d = t & 63;
        float s = 0.f;
        #pragma unroll
        for (int j = 0; j < 16; ++j) s += s_part[j][i][d];
        if (i == 2) s += bv[r * 64 + d];
        g_u[i * D_MODEL + r * 64 + d] = s;
    }
    CLUSTER_SYNC_FENCED();

    // ================= Stage B: w_i = u_i @ Wo ==========================
    for (int k = t; k < D_MODEL; k += 256) {
        s_vec[0][k] = g_u[k];
        s_vec[1][k] = g_u[D_MODEL + k];
        s_vec[2][k] = g_u[2 * D_MODEL + k];
    }
    __syncthreads();
    {
        const int d0 = r * 64 + q * 4;
        float4 a0 = {0,0,0,0}, a1 = {0,0,0,0}, a2 = {0,0,0,0};
        #pragma unroll 8
        for (int i = 0; i < 32; ++i) {
            const int k = ks * 32 + i;
            const float4 w = *(const float4*)&Wo[k * D_MODEL + d0];
            const float x0 = s_vec[0][k], x1 = s_vec[1][k], x2 = s_vec[2][k];
            a0.x = fmaf(x0, w.x, a0.x); a0.y = fmaf(x0, w.y, a0.y);
            a0.z = fmaf(x0, w.z, a0.z); a0.w = fmaf(x0, w.w, a0.w);
            a1.x = fmaf(x1, w.x, a1.x); a1.y = fmaf(x1, w.y, a1.y);
            a1.z = fmaf(x1, w.z, a1.z); a1.w = fmaf(x1, w.w, a1.w);
            a2.x = fmaf(x2, w.x, a2.x); a2.y = fmaf(x2, w.y, a2.y);
            a2.z = fmaf(x2, w.z, a2.z); a2.w = fmaf(x2, w.w, a2.w);
        }
        *(float4*)&s_part[ks][0][q * 4] = a0;
        *(float4*)&s_part[ks][1][q * 4] = a1;
        *(float4*)&s_part[ks][2][q * 4] = a2;
    }
    __syncthreads();
    if (t < 192) {
        const int i = t >> 6, d = t & 63;
        float s = 0.f;
        #pragma unroll
        for (int j = 0; j < 16; ++j) s += s_part[j][i][d];
        if (i == 2) s += bo[r * 64 + d];
        g_w[i * D_MODEL + r * 64 + d] = s;
    }
    CLUSTER_SYNC_FENCED();

    // ========== Stage C+D: head matvec + batch combine (per CTA) =========
    // CTA r -> specialist s = r>>1, head h = r&1 (0=pred, 1=act)
    const int sp = r >> 1, h = r & 1;
    const float* Wh = (h ? act_w : pred_w) + (size_t)sp * D_MODEL * NOUT;
    const float* bh = (h ? act_b : pred_b) + sp * NOUT;

    for (int k = t; k < D_MODEL; k += 256) {
        s_vec[0][k] = g_w[k];
        s_vec[1][k] = g_w[D_MODEL + k];
        s_vec[2][k] = g_w[2 * D_MODEL + k];
    }
    __syncthreads();
    {
        const int o0 = q * 4;
        float4 a0 = {0,0,0,0}, a1 = {0,0,0,0}, a2 = {0,0,0,0};
        #pragma unroll 8
        for (int i = 0; i < 32; ++i) {
            const int k = ks * 32 + i;
            const float4 w = *(const float4*)&Wh[k * NOUT + o0];
            const float x0 = s_vec[0][k], x1 = s_vec[1][k], x2 = s_vec[2][k];
            a0.x = fmaf(x0, w.x, a0.x); a0.y = fmaf(x0, w.y, a0.y);
            a0.z = fmaf(x0, w.z, a0.z); a0.w = fmaf(x0, w.w, a0.w);
            a1.x = fmaf(x1, w.x, a1.x); a1.y = fmaf(x1, w.y, a1.y);
            a1.z = fmaf(x1, w.z, a1.z); a1.w = fmaf(x1, w.w, a1.w);
            a2.x = fmaf(x2, w.x, a2.x); a2.y = fmaf(x2, w.y, a2.y);
            a2.z = fmaf(x2, w.z, a2.z); a2.w = fmaf(x2, w.w, a2.w);
        }
        *(float4*)&s_part[ks][0][q * 4] = a0;
        *(float4*)&s_part[ks][1][q * 4] = a1;
        *(float4*)&s_part[ks][2][q * 4] = a2;
    }
    __syncthreads();
    if (t < 192) {
        const int i = t >> 6, o = t & 63;
        float p = 0.f;
        #pragma unroll
        for (int j = 0; j < 16; ++j) p += s_part[j][i][o];
        if (i == 2) p += bh[o];
        s_P[i][o] = p;
    }
    __syncthreads();
    if (t < NOUT) {
        const float p0 = s_P[0][t], p1 = s_P[1][t], p2 = s_P[2][t];
        #pragma unroll
        for (int b = 0; b < NB; ++b) {
            if (s_sid[b] == sp)
                out[h * NB * NOUT + b * NOUT + t] =
                    fmaf(s_cb[b * 2], p0, fmaf(s_cb[b * 2 + 1], p1, p2));
        }
    }
}

extern "C" void kernel_launch(void* const* d_in, const int* in_sizes, int n_in,
                              void* d_out, int out_size) {
    const float* cb     = (const float*)d_in[1];
    const int*   sid    = (const int*)  d_in[2];
    const float* ctx_w  = (const float*)d_in[16];
    const float* ctx_b  = (const float*)d_in[17];
    const float* ca_wv  = (const float*)d_in[22];
    const float* ca_bv  = (const float*)d_in[23];
    const float* ca_wo  = (const float*)d_in[24];
    const float* ca_bo  = (const float*)d_in[25];
    const float* pred_w = (const float*)d_in[26];
    const float* pred_b = (const float*)d_in[27];
    const float* act_w  = (const float*)d_in[28];
    const float* act_b  = (const float*)d_in[29];
    float* out = (float*)d_out;

    hivemind_cluster<<<NCTA, 256>>>(cb, sid, ctx_w, ctx_b,
                                    ca_wv, ca_bv, ca_wo, ca_bo,
                                    pred_w, pred_b, act_w, act_b, out);
}

// round 8
// speedup vs baseline: 1.0925x; 1.0925x over previous
#include <cuda_runtime.h>
#include <cuda_bf16.h>

// Collapsed forward (linear in context_batch -> batch reduces to 2 scalars):
//   u_i = r_i @ Wv   (r0,r1 = rows of ctx_w, r2 = ctx_b; u2 += bv)
//   w_i = u_i @ Wo   (w2 += bo)
//   P_i[s,h] = w_i @ Whead[s,h]  (+bias)
//   out[h,b,:] = c0[b]*P0 + c1[b]*P1 + P2  (selected by sid[b])
//
// R8: 128 CTAs = 16 clusters x 8. DRAM traffic (3MB, re-read every launch) is
// the floor, so: (a) all 128 SMs stream concurrently, (b) Wo + head tiles are
// cp.async-prefetched at kernel start (barrier-independent), (c) global sync is
// a 2-level hybrid: HW cluster barrier + 16 leader atomics (not 128).

#define D_MODEL 512
#define NB 16
#define NOUT 64
#define NBLK 128
#define NCL 16

__device__ float g_up[8][3][D_MODEL];        // stage-A partials per k-tile
__device__ float g_wp[8][3][D_MODEL];        // stage-B partials per k-tile
__device__ float g_ph[8][8][3][NOUT];        // [cluster(s,h)][rank][i][o]
__device__ unsigned g_bar[2];                // monotonic, graph-replay safe

__device__ __forceinline__ void cp_async16(void* smem_dst, const void* gmem_src) {
    unsigned s = (unsigned)__cvta_generic_to_shared(smem_dst);
    asm volatile("cp.async.cg.shared.global [%0], [%1], 16;" :: "r"(s), "l"(gmem_src));
}

__device__ __forceinline__ void global_sync(int idx) {
    __syncthreads();
    __threadfence();
    asm volatile("barrier.cluster.arrive.aligned;" ::: "memory");
    asm volatile("barrier.cluster.wait.aligned;"   ::: "memory");
    if ((blockIdx.x & 7) == 0 && threadIdx.x == 0) {
        unsigned t = atomicAdd(&g_bar[idx], 1u);
        unsigned R = (t / NCL + 1u) * NCL;
        while (*((volatile unsigned*)&g_bar[idx]) < R) { }
    }
    asm volatile("barrier.cluster.arrive.aligned;" ::: "memory");
    asm volatile("barrier.cluster.wait.aligned;"   ::: "memory");
    __threadfence();
}

__global__ void __cluster_dims__(8, 1, 1) __launch_bounds__(256, 1)
hivemind_r8(
    const float* __restrict__ cb,      // (16,2)
    const int*   __restrict__ sid,     // (16,)
    const float* __restrict__ ctx_w,   // (2,512)
    const float* __restrict__ ctx_b,   // (512,)
    const float* __restrict__ Wv,      // (512,512)
    const float* __restrict__ bv,      // (512,)
    const float* __restrict__ Wo,      // (512,512)
    const float* __restrict__ bo,      // (512,)
    const float* __restrict__ pred_w,  // (4,512,64)
    const float* __restrict__ pred_b,  // (4,64)
    const float* __restrict__ act_w,   // (4,512,64)
    const float* __restrict__ act_b,   // (4,64)
    float* __restrict__ out)           // [pred(16x64), act(16x64)]
{
    __shared__ __align__(16) float s_wo[64][32];   // Wo tile (prefetched)
    __shared__ __align__(16) float s_wh[64][NOUT]; // head tile (prefetched)
    __shared__ float s_x[3][64];                   // stage input slice
    __shared__ float s_part[8][3][32];             // per-warp partials
    __shared__ float s_P[3][NOUT];
    __shared__ float s_cb[NB * 2];
    __shared__ int   s_sid[NB];

    const int blk  = blockIdx.x;
    const int t    = threadIdx.x;
    const int lane = t & 31;
    const int w    = t >> 5;

    const int c  = blk & 15;        // col tile (32 cols) for stages A/B
    const int kt = blk >> 4;        // k tile (64 rows) for stages A/B
    const int kbase = kt * 64;

    // ---- prefetch Wo tile (needed after barrier 0) -----------------------
    // 64 rows x 32 cols = 512 chunks of 16B; 2 per thread
    #pragma unroll
    for (int j = 0; j < 2; ++j) {
        const int id  = t + j * 256;
        const int row = id >> 3, seg = id & 7;
        cp_async16(&s_wo[row][seg * 4],
                   &Wo[(size_t)(kbase + row) * D_MODEL + c * 32 + seg * 4]);
    }
    asm volatile("cp.async.commit_group;" ::: "memory");

    // ---- prefetch head tile (needed after barrier 1; CTAs 0..63 only) ----
    const int cl = blk >> 3;            // cluster id
    const int r8 = blk & 7;             // cluster rank
    if (blk < 64) {
        const int sp = cl >> 1, h = cl & 1;
        const float* Wh = (h ? act_w : pred_w) + (size_t)sp * D_MODEL * NOUT;
        const int kb2 = r8 * 64;
        // 64 rows x 64 cols = 1024 chunks of 16B; 4 per thread
        #pragma unroll
        for (int j = 0; j < 4; ++j) {
            const int id  = t + j * 256;
            const int row = id >> 4, seg = id & 15;
            cp_async16(&s_wh[row][seg * 4],
                       &Wh[(size_t)(kb2 + row) * NOUT + seg * 4]);
        }
    }
    asm volatile("cp.async.commit_group;" ::: "memory");

    if (t < NB * 2) s_cb[t]  = cb[t];
    if (t < NB)     s_sid[t] = sid[t];

    // ================= Stage A: u partials (Wv streamed) =================
    if (t < 64)       s_x[0][t]       = ctx_w[kbase + t];
    else if (t < 128) s_x[1][t - 64]  = ctx_w[D_MODEL + kbase + (t - 64)];
    else if (t < 192) s_x[2][t - 128] = ctx_b[kbase + (t - 128)];
    __syncthreads();
    {
        const float* Wcol = Wv + c * 32 + lane;
        float a0 = 0.f, a1 = 0.f, a2 = 0.f;
        #pragma unroll
        for (int i = 0; i < 8; ++i) {
            const int kl = w * 8 + i;
            const float wt = Wcol[(size_t)(kbase + kl) * D_MODEL];
            a0 = fmaf(s_x[0][kl], wt, a0);
            a1 = fmaf(s_x[1][kl], wt, a1);
            a2 = fmaf(s_x[2][kl], wt, a2);
        }
        s_part[w][0][lane] = a0;
        s_part[w][1][lane] = a1;
        s_part[w][2][lane] = a2;
    }
    __syncthreads();
    if (t < 96) {
        const int i = t >> 5, col = t & 31;
        float s = 0.f;
        #pragma unroll
        for (int j = 0; j < 8; ++j) s += s_part[j][i][col];
        if (i == 2 && kt == 0) s += bv[c * 32 + col];
        g_up[kt][i][c * 32 + col] = s;
    }
    global_sync(0);

    // ================= Stage B: w partials (Wo from smem) ================
    if (t < 192) {
        const int i = t >> 6, kl = t & 63;
        float s = 0.f;
        #pragma unroll
        for (int j = 0; j < 8; ++j) s += g_up[j][i][kbase + kl];
        s_x[i][kl] = s;
    }
    asm volatile("cp.async.wait_group 1;" ::: "memory");   // Wo tile ready
    __syncthreads();
    {
        float a0 = 0.f, a1 = 0.f, a2 = 0.f;
        #pragma unroll
        for (int i = 0; i < 8; ++i) {
            const int kl = w * 8 + i;
            const float wt = s_wo[kl][lane];
            a0 = fmaf(s_x[0][kl], wt, a0);
            a1 = fmaf(s_x[1][kl], wt, a1);
            a2 = fmaf(s_x[2][kl], wt, a2);
        }
        s_part[w][0][lane] = a0;
        s_part[w][1][lane] = a1;
        s_part[w][2][lane] = a2;
    }
    __syncthreads();
    if (t < 96) {
        const int i = t >> 5, col = t & 31;
        float s = 0.f;
        #pragma unroll
        for (int j = 0; j < 8; ++j) s += s_part[j][i][col];
        if (i == 2 && kt == 0) s += bo[c * 32 + col];
        g_wp[kt][i][c * 32 + col] = s;
    }
    global_sync(1);

    // ================= Stage C: heads (tile from smem) ===================
    if (blk >= 64) return;
    const int sp = cl >> 1, h = cl & 1;
    const int kb2 = r8 * 64;

    if (t < 192) {
        const int i = t >> 6, kl = t & 63;
        float s = 0.f;
        #pragma unroll
        for (int j = 0; j < 8; ++j) s += g_wp[j][i][kb2 + kl];
        s_x[i][kl] = s;
    }
    asm volatile("cp.async.wait_group 0;" ::: "memory");   // head tile ready
    __syncthreads();
    {
        // warp w: colhalf = w>>2 (cols 0..31 / 32..63), rowquart = w&3 (16 rows)
        const int colhalf = w >> 2, rq = w & 3;
        const int col = colhalf * 32 + lane;
        float a0 = 0.f, a1 = 0.f, a2 = 0.f;
        #pragma unroll
        for (int i = 0; i < 16; ++i) {
            const int kl = rq * 16 + i;
            const float wt = s_wh[kl][col];
            a0 = fmaf(s_x[0][kl], wt, a0);
            a1 = fmaf(s_x[1][kl], wt, a1);
            a2 = fmaf(s_x[2][kl], wt, a2);
        }
        s_part[w][0][lane] = a0;
        s_part[w][1][lane] = a1;
        s_part[w][2][lane] = a2;
    }
    __syncthreads();
    if (t < 192) {
        const int i = t >> 6, o = t & 63;
        const int ch = o >> 5, l = o & 31;
        float p = s_part[ch * 4 + 0][i][l] + s_part[ch * 4 + 1][i][l]
                + s_part[ch * 4 + 2][i][l] + s_part[ch * 4 + 3][i][l];
        g_ph[cl][r8][i][o] = p;
    }
    __syncthreads();
    __threadfence();
    asm volatile("barrier.cluster.arrive.aligned;" ::: "memory");
    asm volatile("barrier.cluster.wait.aligned;"   ::: "memory");
    __threadfence();

    // ---- rank 0 of each cluster: combine partials + batch output --------
    if (r8 != 0) return;
    const float* bh = (h ? act_b : pred_b) + sp * NOUT;
    if (t < 192) {
        const int i = t >> 6, o = t & 63;
        float p = 0.f;
        #pragma unroll
        for (int j = 0; j < 8; ++j) p += g_ph[cl][j][i][o];
        if (i == 2) p += bh[o];
        s_P[i][o] = p;
    }
    __syncthreads();
    if (t < NOUT) {
        const float p0 = s_P[0][t], p1 = s_P[1][t], p2 = s_P[2][t];
        #pragma unroll
        for (int b = 0; b < NB; ++b) {
            if (s_sid[b] == sp)
                out[h * NB * NOUT + b * NOUT + t] =
                    fmaf(s_cb[b * 2], p0, fmaf(s_cb[b * 2 + 1], p1, p2));
        }
    }
}

extern "C" void kernel_launch(void* const* d_in, const int* in_sizes, int n_in,
                              void* d_out, int out_size) {
    const float* cb     = (const float*)d_in[1];
    const int*   sid    = (const int*)  d_in[2];
    const float* ctx_w  = (const float*)d_in[16];
    const float* ctx_b  = (const float*)d_in[17];
    const float* ca_wv  = (const float*)d_in[22];
    const float* ca_bv  = (const float*)d_in[23];
    const float* ca_wo  = (const float*)d_in[24];
    const float* ca_bo  = (const float*)d_in[25];
    const float* pred_w = (const float*)d_in[26];
    const float* pred_b = (const float*)d_in[27];
    const float* act_w  = (const float*)d_in[28];
    const float* act_b  = (const float*)d_in[29];
    float* out = (float*)d_out;

    hivemind_r8<<<NBLK, 256>>>(cb, sid, ctx_w, ctx_b,
                               ca_wv, ca_bv, ca_wo, ca_bo,
                               pred_w, pred_b, act_w, act_b, out);
}